// round 1
// baseline (speedup 1.0000x reference)
#include <cuda_runtime.h>
#include <cstdint>

#define NB    32
#define CTOT  512
#define GG    8
#define BG    256      // NB*GG
#define CGH   32       // channels per half-group
#define HH    64
#define WW    64
#define PLANE 4096     // HH*WW

// scratch (device globals: no allocation allowed)
__device__ float g_xh[BG * CGH * HH];   // row means of x1
__device__ float g_xw[BG * CGH * WW];   // col means of x1
__device__ float g_xs[BG * CGH];        // plane means of x1
__device__ float g_ah[BG * CGH * HH];   // conv_h output
__device__ float g_aw[BG * CGH * WW];   // conv_w output

__device__ __forceinline__ float sigmoidf_(float z) {
    return __fdividef(1.0f, 1.0f + __expf(-z));
}

// ---------------------------------------------------------------------------
// K1: one 256-thread block per (bg, cc) plane.
//   cc <  32 : channel branch, fully fused (read, reduce, gate, write)
//   cc >= 32 : spatial branch reductions (row/col/total means)
// ---------------------------------------------------------------------------
__global__ __launch_bounds__(256) void k1_kernel(
    const float* __restrict__ x,
    const float* __restrict__ cweight,
    const float* __restrict__ cbias,
    float* __restrict__ out)
{
    const int cc = blockIdx.x;          // 0..63
    const int bg = blockIdx.y;          // 0..255
    const int n  = bg >> 3;
    const int g  = bg & 7;
    const int t  = threadIdx.x;         // 0..255

    const float* p = x + (size_t)(n * CTOT + g * 64 + cc) * PLANE;

    if (cc < CGH) {
        // ---------------- channel branch (x0) ----------------
        const float4* p4 = (const float4*)p;
        float4 v[4];
        float s = 0.f;
        #pragma unroll
        for (int i = 0; i < 4; i++) {
            v[i] = p4[t + 256 * i];
            s += v[i].x + v[i].y + v[i].z + v[i].w;
        }
        __shared__ float ws[8];
        __shared__ float sgate;
        #pragma unroll
        for (int o = 16; o > 0; o >>= 1) s += __shfl_xor_sync(0xffffffffu, s, o);
        if ((t & 31) == 0) ws[t >> 5] = s;
        __syncthreads();
        if (t == 0) {
            float tot = 0.f;
            #pragma unroll
            for (int i = 0; i < 8; i++) tot += ws[i];
            float gap = tot * (1.0f / 4096.0f);
            sgate = sigmoidf_(cweight[cc] * gap + cbias[cc]);
        }
        __syncthreads();
        const float gate = sgate;

        const int c_prev  = g * 64 + cc;
        const int c_final = 2 * (c_prev & 255) + (c_prev >> 8);
        float4* o4 = (float4*)(out + (size_t)(n * CTOT + c_final) * PLANE);
        #pragma unroll
        for (int i = 0; i < 4; i++) {
            float4 r = v[i];
            r.x *= gate; r.y *= gate; r.z *= gate; r.w *= gate;
            o4[t + 256 * i] = r;
        }
    } else {
        // ---------------- spatial branch (x1) reductions ----------------
        // element e = t + 256*i  ->  col = t & 63 (fixed), row = t/64 + 4*i
        const int c1 = cc - CGH;
        float v[16];
        #pragma unroll
        for (int i = 0; i < 16; i++) v[i] = p[t + 256 * i];

        __shared__ float cp[256];       // per-thread column partials
        __shared__ float wsum[16][8];   // per-(i, warp) row partial sums

        float cpv = 0.f;
        #pragma unroll
        for (int i = 0; i < 16; i++) cpv += v[i];
        cp[t] = cpv;

        const int w = t >> 5;
        #pragma unroll
        for (int i = 0; i < 16; i++) {
            float s = v[i];
            #pragma unroll
            for (int o = 16; o > 0; o >>= 1) s += __shfl_xor_sync(0xffffffffu, s, o);
            if ((t & 31) == 0) wsum[i][w] = s;
        }
        __syncthreads();

        const int base = (bg * CGH + c1) * 64;
        if (t < 64) {
            float cs = cp[t] + cp[t + 64] + cp[t + 128] + cp[t + 192];
            g_xw[base + t] = cs * (1.0f / 64.0f);
            // row r = t : i = t/4, q = t%3.. (q = t&3), warps 2q, 2q+1
            const int i = t >> 2, q = t & 3;
            float rs = wsum[i][2 * q] + wsum[i][2 * q + 1];
            g_xh[base + t] = rs * (1.0f / 64.0f);
            cp[t] = cs;   // only owner reads cp[t]; others read t+64k (unwritten) - done above
        }
        __syncthreads();
        if (t == 0) {
            float tot = 0.f;
            #pragma unroll
            for (int i = 0; i < 64; i++) tot += cp[i];
            g_xs[bg * CGH + c1] = tot * (1.0f / 4096.0f);
        }
    }
}

// ---------------------------------------------------------------------------
// K2: conv1x1 -> GroupNorm(per (bg,ch) over 128 pos) -> h-swish -> convh/convw
// one 128-thread block per bg group
// ---------------------------------------------------------------------------
__global__ __launch_bounds__(128) void k2_kernel(
    const float* __restrict__ w1, const float* __restrict__ b1,
    const float* __restrict__ gng, const float* __restrict__ gnb,
    const float* __restrict__ wh, const float* __restrict__ bh,
    const float* __restrict__ wwv, const float* __restrict__ bw)
{
    const int bg = blockIdx.x;     // 0..255
    const int t  = threadIdx.x;    // 0..127

    __shared__ float yin[32][128];
    __shared__ float ybuf[32][128];
    __shared__ float w1s[1024], whs[1024], wws[1024];
    __shared__ float b1s[32], bhs[32], bws[32], gngs[32], gnbs[32];
    __shared__ float mus[32], rstds[32];

    // load inputs: yin[k][p]: p<64 -> x_h, p>=64 -> x_w
    #pragma unroll
    for (int k = 0; k < 32; k++) {
        const int p = t;
        const int src = (bg * CGH + k) * 64;
        yin[k][p] = (p < 64) ? g_xh[src + p] : g_xw[src + p - 64];
    }
    #pragma unroll
    for (int j = 0; j < 8; j++) {
        w1s[t + 128 * j] = w1[t + 128 * j];
        whs[t + 128 * j] = wh[t + 128 * j];
        wws[t + 128 * j] = wwv[t + 128 * j];
    }
    if (t < 32) {
        b1s[t] = b1[t]; bhs[t] = bh[t]; bws[t] = bw[t];
        gngs[t] = gng[t]; gnbs[t] = gnb[t];
    }
    __syncthreads();

    // conv1: each thread owns position p = t across all 32 output channels
    {
        float c[32], acc[32];
        #pragma unroll
        for (int i = 0; i < 32; i++) c[i] = yin[i][t];
        #pragma unroll
        for (int o = 0; o < 32; o++) acc[o] = b1s[o];
        #pragma unroll
        for (int i = 0; i < 32; i++) {
            const float ci = c[i];
            #pragma unroll
            for (int o = 0; o < 32; o++) acc[o] += w1s[o * 32 + i] * ci;
        }
        #pragma unroll
        for (int o = 0; o < 32; o++) ybuf[o][t] = acc[o];
    }
    __syncthreads();

    // GroupNorm stats: warp w handles channels w*8 .. w*8+7
    {
        const int w = t >> 5, l = t & 31;
        #pragma unroll
        for (int j = 0; j < 8; j++) {
            const int o = w * 8 + j;
            float e0 = ybuf[o][l], e1 = ybuf[o][l + 32],
                  e2 = ybuf[o][l + 64], e3 = ybuf[o][l + 96];
            float s  = e0 + e1 + e2 + e3;
            float ss = e0 * e0 + e1 * e1 + e2 * e2 + e3 * e3;
            #pragma unroll
            for (int off = 16; off > 0; off >>= 1) {
                s  += __shfl_xor_sync(0xffffffffu, s, off);
                ss += __shfl_xor_sync(0xffffffffu, ss, off);
            }
            if (l == 0) {
                float mu  = s * (1.0f / 128.0f);
                float var = ss * (1.0f / 128.0f) - mu * mu;
                mus[o] = mu;
                rstds[o] = rsqrtf(var + 1e-5f);
            }
        }
    }
    __syncthreads();

    // normalize + affine + h-swish (in place, column t)
    #pragma unroll
    for (int k = 0; k < 32; k++) {
        float v = (ybuf[k][t] - mus[k]) * rstds[k] * gngs[k] + gnbs[k];
        float hs = fminf(fmaxf(v + 3.0f, 0.0f), 6.0f) * (1.0f / 6.0f);
        ybuf[k][t] = v * hs;
    }
    __syncthreads();

    // convh (positions 0..63) / convw (positions 64..127); position p = t
    {
        const int half = t >> 6;
        const int r = t & 63;
        const float* wsel = half ? wws : whs;
        const float* bsel = half ? bws : bhs;
        float c[32], acc[32];
        #pragma unroll
        for (int i = 0; i < 32; i++) c[i] = ybuf[i][t];
        #pragma unroll
        for (int o = 0; o < 32; o++) acc[o] = bsel[o];
        #pragma unroll
        for (int i = 0; i < 32; i++) {
            const float ci = c[i];
            #pragma unroll
            for (int o = 0; o < 32; o++) acc[o] += wsel[o * 32 + i] * ci;
        }
        float* dst = half ? g_aw : g_ah;
        #pragma unroll
        for (int o = 0; o < 32; o++)
            dst[(bg * CGH + o) * 64 + r] = acc[o];
    }
}

// ---------------------------------------------------------------------------
// K3: spatial gating pass. one 256-thread block per (bg, c1) x1 plane.
// ---------------------------------------------------------------------------
__global__ __launch_bounds__(256) void k3_kernel(
    const float* __restrict__ x,
    float* __restrict__ out)
{
    const int c1 = blockIdx.x;          // 0..31
    const int bg = blockIdx.y;          // 0..255
    const int n  = bg >> 3;
    const int g  = bg & 7;
    const int t  = threadIdx.x;

    __shared__ float sah[64];
    __shared__ float saw[64];
    __shared__ float sxs;

    const int base = (bg * CGH + c1) * 64;
    if (t < 64)            sah[t]       = g_ah[base + t];
    else if (t < 128)      saw[t - 64]  = g_aw[base + t - 64];
    else if (t == 128)     sxs          = g_xs[bg * CGH + c1];
    __syncthreads();

    const float xs = sxs;
    const float4* p4 = (const float4*)(x + (size_t)(n * CTOT + g * 64 + 32 + c1) * PLANE);
    const int c_prev  = g * 64 + 32 + c1;
    const int c_final = 2 * (c_prev & 255) + (c_prev >> 8);
    float4* o4 = (float4*)(out + (size_t)(n * CTOT + c_final) * PLANE);

    const float4 aw4 = ((const float4*)saw)[t & 15];
    #pragma unroll
    for (int i = 0; i < 4; i++) {
        float4 v = p4[t + 256 * i];
        const int row = (t >> 4) + 16 * i;
        const float ah = sah[row] * xs;
        v.x *= sigmoidf_(ah * aw4.x);
        v.y *= sigmoidf_(ah * aw4.y);
        v.z *= sigmoidf_(ah * aw4.z);
        v.w *= sigmoidf_(ah * aw4.w);
        o4[t + 256 * i] = v;
    }
}

// ---------------------------------------------------------------------------
extern "C" void kernel_launch(void* const* d_in, const int* in_sizes, int n_in,
                              void* d_out, int out_size)
{
    const float* x       = (const float*)d_in[0];
    const float* cweight = (const float*)d_in[1];
    const float* cbias   = (const float*)d_in[2];
    const float* conv1_w = (const float*)d_in[3];
    const float* conv1_b = (const float*)d_in[4];
    const float* gn_g    = (const float*)d_in[5];
    const float* gn_b    = (const float*)d_in[6];
    const float* convh_w = (const float*)d_in[7];
    const float* convh_b = (const float*)d_in[8];
    const float* convw_w = (const float*)d_in[9];
    const float* convw_b = (const float*)d_in[10];
    float* out = (float*)d_out;

    dim3 g1(64, BG);
    k1_kernel<<<g1, 256>>>(x, cweight, cbias, out);
    k2_kernel<<<BG, 128>>>(conv1_w, conv1_b, gn_g, gn_b,
                           convh_w, convh_b, convw_w, convw_b);
    dim3 g3(CGH, BG);
    k3_kernel<<<g3, 256>>>(x, out);
}

// round 2
// speedup vs baseline: 1.0178x; 1.0178x over previous
#include <cuda_runtime.h>
#include <cstdint>

#define NB    32
#define CTOT  512
#define GG    8
#define BG    256      // NB*GG
#define CGH   32       // channels per half-group
#define HH    64
#define WW    64
#define PLANE 4096     // HH*WW

// scratch (device globals: no allocation allowed)
__device__ float g_xh[BG * CGH * HH];   // row means of x1
__device__ float g_xw[BG * CGH * WW];   // col means of x1
__device__ float g_xs[BG * CGH];        // plane means of x1
__device__ float g_ah[BG * CGH * HH];   // conv_h output
__device__ float g_aw[BG * CGH * WW];   // conv_w output

__device__ __forceinline__ float sigmoid_exact(float z) {
    return __fdividef(1.0f, 1.0f + __expf(-z));
}

// 1-MUFU sigmoid: sigmoid(z) = 0.5*tanh(z/2) + 0.5  (tanh.approx, ~3e-4 abs err)
__device__ __forceinline__ float sigmoid_fast(float z) {
    float t;
    asm("tanh.approx.f32 %0, %1;" : "=f"(t) : "f"(z * 0.5f));
    return fmaf(0.5f, t, 0.5f);
}

// ---------------------------------------------------------------------------
// K1: one 256-thread block per (bg, cc) plane.
//   cc <  32 : channel branch, fully fused (read, reduce, gate, write)
//   cc >= 32 : spatial branch reductions (row/col/total means), all float4
// ---------------------------------------------------------------------------
__global__ __launch_bounds__(256) void k1_kernel(
    const float* __restrict__ x,
    const float* __restrict__ cweight,
    const float* __restrict__ cbias,
    float* __restrict__ out)
{
    const int cc = blockIdx.x;          // 0..63
    const int bg = blockIdx.y;          // 0..255
    const int n  = bg >> 3;
    const int g  = bg & 7;
    const int t  = threadIdx.x;         // 0..255

    const float4* p4 = (const float4*)(x + (size_t)(n * CTOT + g * 64 + cc) * PLANE);

    float4 v[4];
    #pragma unroll
    for (int i = 0; i < 4; i++) v[i] = p4[t + 256 * i];

    if (cc < CGH) {
        // ---------------- channel branch (x0) ----------------
        float s = 0.f;
        #pragma unroll
        for (int i = 0; i < 4; i++) s += v[i].x + v[i].y + v[i].z + v[i].w;
        __shared__ float ws[8];
        __shared__ float sgate;
        #pragma unroll
        for (int o = 16; o > 0; o >>= 1) s += __shfl_xor_sync(0xffffffffu, s, o);
        if ((t & 31) == 0) ws[t >> 5] = s;
        __syncthreads();
        if (t == 0) {
            float tot = 0.f;
            #pragma unroll
            for (int i = 0; i < 8; i++) tot += ws[i];
            float gap = tot * (1.0f / 4096.0f);
            sgate = sigmoid_exact(cweight[cc] * gap + cbias[cc]);
        }
        __syncthreads();
        const float gate = sgate;

        const int c_prev  = g * 64 + cc;
        const int c_final = 2 * (c_prev & 255) + (c_prev >> 8);
        float4* o4 = (float4*)(out + (size_t)(n * CTOT + c_final) * PLANE);
        #pragma unroll
        for (int i = 0; i < 4; i++) {
            float4 r = v[i];
            r.x *= gate; r.y *= gate; r.z *= gate; r.w *= gate;
            o4[t + 256 * i] = r;
        }
    } else {
        // ---------------- spatial branch (x1) reductions ----------------
        // float4 j = t + 256*i : row = (t>>4) + 16*i, cols 4*(t&15)..+3
        const int c1   = cc - CGH;
        const int base = (bg * CGH + c1) * 64;

        // row sums: reduce over 16-lane groups sharing t>>4
        #pragma unroll
        for (int i = 0; i < 4; i++) {
            float s = v[i].x + v[i].y + v[i].z + v[i].w;
            #pragma unroll
            for (int o = 8; o > 0; o >>= 1) s += __shfl_xor_sync(0xffffffffu, s, o);
            if ((t & 15) == 0)
                g_xh[base + (t >> 4) + 16 * i] = s * (1.0f / 64.0f);
        }

        // column partials: acc4 holds per-thread sums for its 4 columns
        float4 acc;
        acc.x = v[0].x + v[1].x + v[2].x + v[3].x;
        acc.y = v[0].y + v[1].y + v[2].y + v[3].y;
        acc.z = v[0].z + v[1].z + v[2].z + v[3].z;
        acc.w = v[0].w + v[1].w + v[2].w + v[3].w;

        __shared__ float4 cp4[256];
        __shared__ float part[2];
        cp4[t] = acc;
        __syncthreads();

        if (t < 64) {
            // column t: fold 16 contributors (threads k*16 + t>>2, component t&3)
            const int grp = t >> 2, comp = t & 3;
            const float* cpf = (const float*)cp4;
            float cs = 0.f;
            #pragma unroll
            for (int k = 0; k < 16; k++)
                cs += cpf[(k * 16 + grp) * 4 + comp];
            g_xw[base + t] = cs * (1.0f / 64.0f);

            float s2 = cs;
            #pragma unroll
            for (int o = 16; o > 0; o >>= 1) s2 += __shfl_xor_sync(0xffffffffu, s2, o);
            if ((t & 31) == 0) part[t >> 5] = s2;
        }
        __syncthreads();
        if (t == 0)
            g_xs[bg * CGH + c1] = (part[0] + part[1]) * (1.0f / 4096.0f);
    }
}

// ---------------------------------------------------------------------------
// K2: conv1x1 -> GroupNorm -> h-swish -> convh/convw. One 128-thread block
// per bg group. PDL: weight loads before grid-dependency sync.
// ---------------------------------------------------------------------------
__global__ __launch_bounds__(128) void k2_kernel(
    const float* __restrict__ w1, const float* __restrict__ b1,
    const float* __restrict__ gng, const float* __restrict__ gnb,
    const float* __restrict__ wh, const float* __restrict__ bh,
    const float* __restrict__ wwv, const float* __restrict__ bw)
{
    const int bg = blockIdx.x;     // 0..255
    const int t  = threadIdx.x;    // 0..127

    __shared__ float yin[32][128];
    __shared__ float ybuf[32][128];
    __shared__ float w1s[1024], whs[1024], wws[1024];
    __shared__ float b1s[32], bhs[32], bws[32], gngs[32], gnbs[32];
    __shared__ float mus[32], rstds[32];

    // independent prologue: weights (do not depend on K1)
    #pragma unroll
    for (int j = 0; j < 8; j++) {
        w1s[t + 128 * j] = w1[t + 128 * j];
        whs[t + 128 * j] = wh[t + 128 * j];
        wws[t + 128 * j] = wwv[t + 128 * j];
    }
    if (t < 32) {
        b1s[t] = b1[t]; bhs[t] = bh[t]; bws[t] = bw[t];
        gngs[t] = gng[t]; gnbs[t] = gnb[t];
    }

    cudaGridDependencySynchronize();   // wait for K1's g_xh/g_xw

    // load inputs: yin[k][p]: p<64 -> x_h, p>=64 -> x_w
    #pragma unroll
    for (int k = 0; k < 32; k++) {
        const int src = (bg * CGH + k) * 64;
        yin[k][t] = (t < 64) ? g_xh[src + t] : g_xw[src + t - 64];
    }
    __syncthreads();

    // conv1: thread owns position p = t across all 32 output channels
    {
        float c[32], acc[32];
        #pragma unroll
        for (int i = 0; i < 32; i++) c[i] = yin[i][t];
        #pragma unroll
        for (int o = 0; o < 32; o++) acc[o] = b1s[o];
        #pragma unroll
        for (int i = 0; i < 32; i++) {
            const float ci = c[i];
            #pragma unroll
            for (int o = 0; o < 32; o++) acc[o] += w1s[o * 32 + i] * ci;
        }
        #pragma unroll
        for (int o = 0; o < 32; o++) ybuf[o][t] = acc[o];
    }
    __syncthreads();

    // GroupNorm stats: warp w handles channels w*8 .. w*8+7
    {
        const int w = t >> 5, l = t & 31;
        #pragma unroll
        for (int j = 0; j < 8; j++) {
            const int o = w * 8 + j;
            float e0 = ybuf[o][l], e1 = ybuf[o][l + 32],
                  e2 = ybuf[o][l + 64], e3 = ybuf[o][l + 96];
            float s  = e0 + e1 + e2 + e3;
            float ss = e0 * e0 + e1 * e1 + e2 * e2 + e3 * e3;
            #pragma unroll
            for (int off = 16; off > 0; off >>= 1) {
                s  += __shfl_xor_sync(0xffffffffu, s, off);
                ss += __shfl_xor_sync(0xffffffffu, ss, off);
            }
            if (l == 0) {
                float mu  = s * (1.0f / 128.0f);
                float var = ss * (1.0f / 128.0f) - mu * mu;
                mus[o] = mu;
                rstds[o] = rsqrtf(var + 1e-5f);
            }
        }
    }
    __syncthreads();

    // normalize + affine + h-swish (column t)
    #pragma unroll
    for (int k = 0; k < 32; k++) {
        float v = (ybuf[k][t] - mus[k]) * rstds[k] * gngs[k] + gnbs[k];
        float hs = fminf(fmaxf(v + 3.0f, 0.0f), 6.0f) * (1.0f / 6.0f);
        ybuf[k][t] = v * hs;
    }
    __syncthreads();

    // convh (p<64) / convw (p>=64)
    {
        const int half = t >> 6;
        const int r = t & 63;
        const float* wsel = half ? wws : whs;
        const float* bsel = half ? bws : bhs;
        float c[32], acc[32];
        #pragma unroll
        for (int i = 0; i < 32; i++) c[i] = ybuf[i][t];
        #pragma unroll
        for (int o = 0; o < 32; o++) acc[o] = bsel[o];
        #pragma unroll
        for (int i = 0; i < 32; i++) {
            const float ci = c[i];
            #pragma unroll
            for (int o = 0; o < 32; o++) acc[o] += wsel[o * 32 + i] * ci;
        }
        float* dst = half ? g_aw : g_ah;
        #pragma unroll
        for (int o = 0; o < 32; o++)
            dst[(bg * CGH + o) * 64 + r] = acc[o];
    }
    cudaTriggerProgrammaticLaunchCompletion();
}

// ---------------------------------------------------------------------------
// K3: spatial gating pass. Plane loads issued BEFORE the grid-dependency
// sync so the 16 KB x1 stream overlaps K2 drain + launch latency.
// ---------------------------------------------------------------------------
__global__ __launch_bounds__(256) void k3_kernel(
    const float* __restrict__ x,
    float* __restrict__ out)
{
    const int c1 = blockIdx.x;          // 0..31
    const int bg = blockIdx.y;          // 0..255
    const int n  = bg >> 3;
    const int g  = bg & 7;
    const int t  = threadIdx.x;

    // independent prologue: x1 plane prefetch
    const float4* p4 = (const float4*)(x + (size_t)(n * CTOT + g * 64 + 32 + c1) * PLANE);
    float4 v[4];
    #pragma unroll
    for (int i = 0; i < 4; i++) v[i] = p4[t + 256 * i];

    cudaGridDependencySynchronize();    // wait for K2's g_ah/g_aw/g_xs

    __shared__ float sah[64];
    __shared__ float saw[64];
    __shared__ float sxs;

    const int base = (bg * CGH + c1) * 64;
    if (t < 64)            sah[t]       = g_ah[base + t];
    else if (t < 128)      saw[t - 64]  = g_aw[base + t - 64];
    else if (t == 128)     sxs          = g_xs[bg * CGH + c1];
    __syncthreads();

    const float xs = sxs;
    const int c_prev  = g * 64 + 32 + c1;
    const int c_final = 2 * (c_prev & 255) + (c_prev >> 8);
    float4* o4 = (float4*)(out + (size_t)(n * CTOT + c_final) * PLANE);

    const float4 aw4 = ((const float4*)saw)[t & 15];
    #pragma unroll
    for (int i = 0; i < 4; i++) {
        float4 r = v[i];
        const int row = (t >> 4) + 16 * i;
        const float ah = sah[row] * xs;
        r.x *= sigmoid_fast(ah * aw4.x);
        r.y *= sigmoid_fast(ah * aw4.y);
        r.z *= sigmoid_fast(ah * aw4.z);
        r.w *= sigmoid_fast(ah * aw4.w);
        o4[t + 256 * i] = r;
    }
}

// ---------------------------------------------------------------------------
extern "C" void kernel_launch(void* const* d_in, const int* in_sizes, int n_in,
                              void* d_out, int out_size)
{
    const float* x       = (const float*)d_in[0];
    const float* cweight = (const float*)d_in[1];
    const float* cbias   = (const float*)d_in[2];
    const float* conv1_w = (const float*)d_in[3];
    const float* conv1_b = (const float*)d_in[4];
    const float* gn_g    = (const float*)d_in[5];
    const float* gn_b    = (const float*)d_in[6];
    const float* convh_w = (const float*)d_in[7];
    const float* convh_b = (const float*)d_in[8];
    const float* convw_w = (const float*)d_in[9];
    const float* convw_b = (const float*)d_in[10];
    float* out = (float*)d_out;

    dim3 g1(64, BG);
    k1_kernel<<<g1, 256>>>(x, cweight, cbias, out);

    cudaLaunchAttribute pdl[1];
    pdl[0].id = cudaLaunchAttributeProgrammaticStreamSerialization;
    pdl[0].val.programmaticStreamSerializationAllowed = 1;

    cudaLaunchConfig_t cfg2 = {};
    cfg2.gridDim  = dim3(BG, 1, 1);
    cfg2.blockDim = dim3(128, 1, 1);
    cfg2.stream   = 0;
    cfg2.attrs    = pdl;
    cfg2.numAttrs = 1;
    cudaLaunchKernelEx(&cfg2, k2_kernel, conv1_w, conv1_b, gn_g, gn_b,
                       convh_w, convh_b, convw_w, convw_b);

    cudaLaunchConfig_t cfg3 = {};
    cfg3.gridDim  = dim3(CGH, BG, 1);
    cfg3.blockDim = dim3(256, 1, 1);
    cfg3.stream   = 0;
    cfg3.attrs    = pdl;
    cfg3.numAttrs = 1;
    cudaLaunchKernelEx(&cfg3, k3_kernel, x, out);
}

// round 4
// speedup vs baseline: 1.0365x; 1.0184x over previous
#include <cuda_runtime.h>
#include <cstdint>

#define NB    32
#define CTOT  512
#define GG    8
#define BG    256      // NB*GG
#define CGH   32       // channels per half-group
#define HH    64
#define WW    64
#define PLANE 4096     // HH*WW

// scratch (device globals: no allocation allowed)
__device__ float g_xh[BG * CGH * HH];   // row means of x1
__device__ float g_xw[BG * CGH * WW];   // col means of x1
__device__ float g_xs[BG * CGH];        // plane means of x1
__device__ float g_ah[BG * CGH * HH];   // conv_h output
__device__ float g_aw[BG * CGH * WW];   // conv_w output

__device__ __forceinline__ float sigmoid_exact(float z) {
    return __fdividef(1.0f, 1.0f + __expf(-z));
}

// 1-MUFU sigmoid: sigmoid(z) = 0.5*tanh(z/2) + 0.5
__device__ __forceinline__ float sigmoid_fast(float z) {
    float t;
    asm("tanh.approx.f32 %0, %1;" : "=f"(t) : "f"(z * 0.5f));
    return fmaf(0.5f, t, 0.5f);
}

// ---------------------------------------------------------------------------
// K1: one 256-thread block per (bg, cc) plane.
//   cc <  32 : channel branch, fully fused (read, reduce, gate, write)
//   cc >= 32 : spatial branch reductions (row/col/total means), all float4
// ---------------------------------------------------------------------------
__global__ __launch_bounds__(256) void k1_kernel(
    const float* __restrict__ x,
    const float* __restrict__ cweight,
    const float* __restrict__ cbias,
    float* __restrict__ out)
{
    const int cc = blockIdx.x;          // 0..63
    const int bg = blockIdx.y;          // 0..255
    const int n  = bg >> 3;
    const int g  = bg & 7;
    const int t  = threadIdx.x;         // 0..255

    const float4* p4 = (const float4*)(x + (size_t)(n * CTOT + g * 64 + cc) * PLANE);

    float4 v[4];
    #pragma unroll
    for (int i = 0; i < 4; i++) v[i] = p4[t + 256 * i];

    if (cc < CGH) {
        // ---------------- channel branch (x0) ----------------
        float s = 0.f;
        #pragma unroll
        for (int i = 0; i < 4; i++) s += v[i].x + v[i].y + v[i].z + v[i].w;
        __shared__ float ws[8];
        __shared__ float sgate;
        #pragma unroll
        for (int o = 16; o > 0; o >>= 1) s += __shfl_xor_sync(0xffffffffu, s, o);
        if ((t & 31) == 0) ws[t >> 5] = s;
        __syncthreads();
        if (t == 0) {
            float tot = 0.f;
            #pragma unroll
            for (int i = 0; i < 8; i++) tot += ws[i];
            float gap = tot * (1.0f / 4096.0f);
            sgate = sigmoid_exact(cweight[cc] * gap + cbias[cc]);
        }
        __syncthreads();
        const float gate = sgate;

        const int c_prev  = g * 64 + cc;
        const int c_final = 2 * (c_prev & 255) + (c_prev >> 8);
        float4* o4 = (float4*)(out + (size_t)(n * CTOT + c_final) * PLANE);
        #pragma unroll
        for (int i = 0; i < 4; i++) {
            float4 r = v[i];
            r.x *= gate; r.y *= gate; r.z *= gate; r.w *= gate;
            o4[t + 256 * i] = r;
        }
    } else {
        // ---------------- spatial branch (x1) reductions ----------------
        // float4 j = t + 256*i : row = (t>>4) + 16*i, cols 4*(t&15)..+3
        const int c1   = cc - CGH;
        const int base = (bg * CGH + c1) * 64;

        // row sums: reduce over 16-lane groups sharing t>>4
        #pragma unroll
        for (int i = 0; i < 4; i++) {
            float s = v[i].x + v[i].y + v[i].z + v[i].w;
            #pragma unroll
            for (int o = 8; o > 0; o >>= 1) s += __shfl_xor_sync(0xffffffffu, s, o);
            if ((t & 15) == 0)
                g_xh[base + (t >> 4) + 16 * i] = s * (1.0f / 64.0f);
        }

        // column partials
        float4 acc;
        acc.x = v[0].x + v[1].x + v[2].x + v[3].x;
        acc.y = v[0].y + v[1].y + v[2].y + v[3].y;
        acc.z = v[0].z + v[1].z + v[2].z + v[3].z;
        acc.w = v[0].w + v[1].w + v[2].w + v[3].w;

        __shared__ float4 cp4[256];
        __shared__ float part[2];
        cp4[t] = acc;
        __syncthreads();

        if (t < 64) {
            const int grp = t >> 2, comp = t & 3;
            const float* cpf = (const float*)cp4;
            float cs = 0.f;
            #pragma unroll
            for (int k = 0; k < 16; k++)
                cs += cpf[(k * 16 + grp) * 4 + comp];
            g_xw[base + t] = cs * (1.0f / 64.0f);

            float s2 = cs;
            #pragma unroll
            for (int o = 16; o > 0; o >>= 1) s2 += __shfl_xor_sync(0xffffffffu, s2, o);
            if ((t & 31) == 0) part[t >> 5] = s2;
        }
        __syncthreads();
        if (t == 0)
            g_xs[bg * CGH + c1] = (part[0] + part[1]) * (1.0f / 4096.0f);
    }
}

// ---------------------------------------------------------------------------
// K2: conv1x1 -> GroupNorm -> h-swish -> convh/convw. One 256-thread block
// per bg group; output channels split 16/16 across thread halves.
// ---------------------------------------------------------------------------
__global__ __launch_bounds__(256) void k2_kernel(
    const float* __restrict__ w1, const float* __restrict__ b1,
    const float* __restrict__ gng, const float* __restrict__ gnb,
    const float* __restrict__ wh, const float* __restrict__ bh,
    const float* __restrict__ wwv, const float* __restrict__ bw)
{
    const int bg = blockIdx.x;     // 0..255
    const int t  = threadIdx.x;    // 0..255
    const int p  = t & 127;        // position 0..127
    const int oh = (t >> 7) * 16;  // output-channel half base: 0 or 16

    __shared__ float yin[32][128];
    __shared__ float ybuf[32][128];
    __shared__ float w1s[1024], whs[1024], wws[1024];
    __shared__ float b1s[32], bhs[32], bws[32], gngs[32], gnbs[32];
    __shared__ float mus[32], rstds[32];

    // independent prologue: weights (do not depend on K1)
    #pragma unroll
    for (int j = 0; j < 4; j++) {
        w1s[t + 256 * j] = w1[t + 256 * j];
        whs[t + 256 * j] = wh[t + 256 * j];
        wws[t + 256 * j] = wwv[t + 256 * j];
    }
    if (t < 32) {
        b1s[t] = b1[t]; bhs[t] = bh[t]; bws[t] = bw[t];
        gngs[t] = gng[t]; gnbs[t] = gnb[t];
    }

    cudaGridDependencySynchronize();   // wait for K1's g_xh/g_xw

    // load inputs: yin[k][p]: p<64 -> x_h, p>=64 -> x_w  (threads t<128 only)
    if (t < 128) {
        #pragma unroll
        for (int k = 0; k < 32; k++) {
            const int src = (bg * CGH + k) * 64;
            yin[k][p] = (p < 64) ? g_xh[src + p] : g_xw[src + p - 64];
        }
    }
    __syncthreads();

    // conv1: thread owns position p, outputs oh..oh+15
    {
        float c[32], acc[16];
        #pragma unroll
        for (int i = 0; i < 32; i++) c[i] = yin[i][p];
        #pragma unroll
        for (int o = 0; o < 16; o++) acc[o] = b1s[oh + o];
        #pragma unroll
        for (int i = 0; i < 32; i++) {
            const float ci = c[i];
            #pragma unroll
            for (int o = 0; o < 16; o++) acc[o] += w1s[(oh + o) * 32 + i] * ci;
        }
        #pragma unroll
        for (int o = 0; o < 16; o++) ybuf[oh + o][p] = acc[o];
    }
    __syncthreads();

    // GroupNorm stats: 8 warps, warp w handles channels w*4 .. w*4+3
    {
        const int w = t >> 5, l = t & 31;
        #pragma unroll
        for (int j = 0; j < 4; j++) {
            const int o = w * 4 + j;
            float e0 = ybuf[o][l], e1 = ybuf[o][l + 32],
                  e2 = ybuf[o][l + 64], e3 = ybuf[o][l + 96];
            float s  = e0 + e1 + e2 + e3;
            float ss = e0 * e0 + e1 * e1 + e2 * e2 + e3 * e3;
            #pragma unroll
            for (int off = 16; off > 0; off >>= 1) {
                s  += __shfl_xor_sync(0xffffffffu, s, off);
                ss += __shfl_xor_sync(0xffffffffu, ss, off);
            }
            if (l == 0) {
                float mu  = s * (1.0f / 128.0f);
                float var = ss * (1.0f / 128.0f) - mu * mu;
                mus[o] = mu;
                rstds[o] = rsqrtf(var + 1e-5f);
            }
        }
    }
    __syncthreads();

    // normalize + affine + h-swish: thread handles channels oh..oh+15 at p
    #pragma unroll
    for (int j = 0; j < 16; j++) {
        const int k = oh + j;
        float v = (ybuf[k][p] - mus[k]) * rstds[k] * gngs[k] + gnbs[k];
        float hs = fminf(fmaxf(v + 3.0f, 0.0f), 6.0f) * (1.0f / 6.0f);
        ybuf[k][p] = v * hs;
    }
    __syncthreads();

    // convh (p<64) / convw (p>=64): outputs oh..oh+15 at position p
    {
        const int half = p >> 6;
        const int r = p & 63;
        const float* wsel = half ? wws : whs;
        const float* bsel = half ? bws : bhs;
        float c[32], acc[16];
        #pragma unroll
        for (int i = 0; i < 32; i++) c[i] = ybuf[i][p];
        #pragma unroll
        for (int o = 0; o < 16; o++) acc[o] = bsel[oh + o];
        #pragma unroll
        for (int i = 0; i < 32; i++) {
            const float ci = c[i];
            #pragma unroll
            for (int o = 0; o < 16; o++) acc[o] += wsel[(oh + o) * 32 + i] * ci;
        }
        float* dst = half ? g_aw : g_ah;
        #pragma unroll
        for (int o = 0; o < 16; o++)
            dst[(bg * CGH + oh + o) * 64 + r] = acc[o];
    }
    cudaTriggerProgrammaticLaunchCompletion();
}

// ---------------------------------------------------------------------------
// K3: spatial gating pass. No smem, no __syncthreads: every thread loads its
// own gate values to registers right after the grid-dependency sync.
// ---------------------------------------------------------------------------
__global__ __launch_bounds__(256) void k3_kernel(
    const float* __restrict__ x,
    float* __restrict__ out)
{
    const int c1 = blockIdx.x;          // 0..31
    const int bg = blockIdx.y;          // 0..255
    const int n  = bg >> 3;
    const int g  = bg & 7;
    const int t  = threadIdx.x;

    // independent prologue: x1 plane prefetch (overlaps producer drain)
    const float4* p4 = (const float4*)(x + (size_t)(n * CTOT + g * 64 + 32 + c1) * PLANE);
    float4 v[4];
    #pragma unroll
    for (int i = 0; i < 4; i++) v[i] = p4[t + 256 * i];

    cudaGridDependencySynchronize();    // wait for K2's g_ah/g_aw/g_xs

    const int base = (bg * CGH + c1) * 64;

    // per-thread gate loads (L2-resident; broadcast within lane groups)
    const float  xs  = __ldg(&g_xs[bg * CGH + c1]);
    const float4 aw4 = __ldg((const float4*)g_aw + (base >> 2) + (t & 15));
    float ah[4];
    #pragma unroll
    for (int i = 0; i < 4; i++)
        ah[i] = __ldg(&g_ah[base + (t >> 4) + 16 * i]) * xs;

    const int c_prev  = g * 64 + 32 + c1;
    const int c_final = 2 * (c_prev & 255) + (c_prev >> 8);
    float4* o4 = (float4*)(out + (size_t)(n * CTOT + c_final) * PLANE);

    #pragma unroll
    for (int i = 0; i < 4; i++) {
        float4 r = v[i];
        r.x *= sigmoid_fast(ah[i] * aw4.x);
        r.y *= sigmoid_fast(ah[i] * aw4.y);
        r.z *= sigmoid_fast(ah[i] * aw4.z);
        r.w *= sigmoid_fast(ah[i] * aw4.w);
        o4[t + 256 * i] = r;
    }
}

// ---------------------------------------------------------------------------
extern "C" void kernel_launch(void* const* d_in, const int* in_sizes, int n_in,
                              void* d_out, int out_size)
{
    const float* x       = (const float*)d_in[0];
    const float* cweight = (const float*)d_in[1];
    const float* cbias   = (const float*)d_in[2];
    const float* conv1_w = (const float*)d_in[3];
    const float* conv1_b = (const float*)d_in[4];
    const float* gn_g    = (const float*)d_in[5];
    const float* gn_b    = (const float*)d_in[6];
    const float* convh_w = (const float*)d_in[7];
    const float* convh_b = (const float*)d_in[8];
    const float* convw_w = (const float*)d_in[9];
    const float* convw_b = (const float*)d_in[10];
    float* out = (float*)d_out;

    dim3 g1(64, BG);
    k1_kernel<<<g1, 256>>>(x, cweight, cbias, out);

    cudaLaunchAttribute pdl[1];
    pdl[0].id = cudaLaunchAttributeProgrammaticStreamSerialization;
    pdl[0].val.programmaticStreamSerializationAllowed = 1;

    cudaLaunchConfig_t cfg2 = {};
    cfg2.gridDim  = dim3(BG, 1, 1);
    cfg2.blockDim = dim3(256, 1, 1);
    cfg2.stream   = 0;
    cfg2.attrs    = pdl;
    cfg2.numAttrs = 1;
    cudaLaunchKernelEx(&cfg2, k2_kernel, conv1_w, conv1_b, gn_g, gn_b,
                       convh_w, convh_b, convw_w, convw_b);

    cudaLaunchConfig_t cfg3 = {};
    cfg3.gridDim  = dim3(CGH, BG, 1);
    cfg3.blockDim = dim3(256, 1, 1);
    cfg3.stream   = 0;
    cfg3.attrs    = pdl;
    cfg3.numAttrs = 1;
    cudaLaunchKernelEx(&cfg3, k3_kernel, x, out);
}